// round 8
// baseline (speedup 1.0000x reference)
#include <cuda_runtime.h>

// FraudDetectionModel R8: single graph node, reduced-CTA persistent style.
//  Theory: R2(67% DRAM, 32.2us) vs R5/R7(62%, 34.4us) differ ONLY in the
//  per-CTA thread0-fold + __syncthreads prologue. 16384 CTAs each paying a
//  serialized ~43-LDG fold = dead memory-pipe time. Fix: 2048 CTAs x 8
//  iterations -> fold cost amortized 8x; prefetch next iteration's loads to
//  keep the memory queue fed.

#define BATCH   16777216
#define THREADS 256
#define BLOCKS  2048
#define ITERS   8
// work item = 4 rows = 2 float4 in, 1 float4 out
// BLOCKS*THREADS*ITERS = 4,194,304 = BATCH/4 exactly.

__device__ __forceinline__ float fast_tanh(float x) {
    float y;
    asm("tanh.approx.f32 %0, %1;" : "=f"(y) : "f"(x));
    return y;
}

// smem param layout, 8 floats per layer:
//   layer l (0..3) at [8l]: w00 w01 w10 w11 b0 b1 pad pad
//   final at [32]:          wf0 wf1 bf pad
__global__ void __launch_bounds__(THREADS)
fraud_mlp_kernel(const float4* __restrict__ x,    // [B/2] row pairs
                 float4*       __restrict__ out,  // [B/4] quad outputs
                 const float*  __restrict__ Ws,   // [4,2,2]
                 const float*  __restrict__ bs,   // [4,2]
                 const float*  __restrict__ sc,   // [4,2]
                 const float*  __restrict__ sh,   // [4,2]
                 const float*  __restrict__ Wf,   // [1,2]
                 const float*  __restrict__ bf)   // [1]
{
    __shared__ __align__(16) float p[36];

    const int stride = BLOCKS * THREADS;                       // 524288 items
    int item = blockIdx.x * THREADS + threadIdx.x;

    // Prefetch iteration 0 BEFORE the barrier (overlaps the fold).
    float4 a = x[2 * item + 0];
    float4 b = x[2 * item + 1];

    if (threadIdx.x == 0) {
        // layer 0 unchanged
        p[0] = __ldg(Ws + 0); p[1] = __ldg(Ws + 1);
        p[2] = __ldg(Ws + 2); p[3] = __ldg(Ws + 3);
        p[4] = __ldg(bs + 0); p[5] = __ldg(bs + 1);
        p[6] = 0.f; p[7] = 0.f;

        // layers 1..3: W'_l = W_l * diag(s_{l-1}); b'_l = W_l t_{l-1} + b_l
#pragma unroll
        for (int l = 1; l < 4; l++) {
            const float w00 = __ldg(Ws + l * 4 + 0), w01 = __ldg(Ws + l * 4 + 1);
            const float w10 = __ldg(Ws + l * 4 + 2), w11 = __ldg(Ws + l * 4 + 3);
            const float sp0 = __ldg(sc + (l - 1) * 2 + 0), sp1 = __ldg(sc + (l - 1) * 2 + 1);
            const float tp0 = __ldg(sh + (l - 1) * 2 + 0), tp1 = __ldg(sh + (l - 1) * 2 + 1);
            p[l * 8 + 0] = w00 * sp0;
            p[l * 8 + 1] = w01 * sp1;
            p[l * 8 + 2] = w10 * sp0;
            p[l * 8 + 3] = w11 * sp1;
            p[l * 8 + 4] = fmaf(w00, tp0, fmaf(w01, tp1, __ldg(bs + l * 2 + 0)));
            p[l * 8 + 5] = fmaf(w10, tp0, fmaf(w11, tp1, __ldg(bs + l * 2 + 1)));
            p[l * 8 + 6] = 0.f; p[l * 8 + 7] = 0.f;
        }

        // final: wf' = Wf * diag(s_3); bf' = Wf t_3 + bf
        const float s30 = __ldg(sc + 6), s31 = __ldg(sc + 7);
        const float t30 = __ldg(sh + 6), t31 = __ldg(sh + 7);
        const float f0 = __ldg(Wf + 0), f1 = __ldg(Wf + 1);
        p[32] = f0 * s30;
        p[33] = f1 * s31;
        p[34] = fmaf(f0, t30, fmaf(f1, t31, __ldg(bf)));
        p[35] = 0.0f;
    }
    __syncthreads();

    const float4* pv = reinterpret_cast<const float4*>(p);

#pragma unroll 1
    for (int it = 0; it < ITERS; it++) {
        const int next = item + stride;

        // Prefetch next iteration's loads so the memory queue stays fed
        // while this iteration computes.
        float4 an, bn;
        if (it + 1 < ITERS) {
            an = x[2 * next + 0];
            bn = x[2 * next + 1];
        }

        float ha[4], hb[4];
        ha[0] = a.x; hb[0] = a.y;  ha[1] = a.z; hb[1] = a.w;
        ha[2] = b.x; hb[2] = b.y;  ha[3] = b.z; hb[3] = b.w;

#pragma unroll
        for (int l = 0; l < 4; l++) {
            const float4 wv = pv[2 * l + 0];   // w00 w01 w10 w11
            const float4 bv = pv[2 * l + 1];   // b0 b1 - -
#pragma unroll
            for (int r = 0; r < 4; r++) {
                float u0 = fmaf(wv.x, ha[r], fmaf(wv.y, hb[r], bv.x));
                float u1 = fmaf(wv.z, ha[r], fmaf(wv.w, hb[r], bv.y));
                ha[r] = fast_tanh(u0);
                hb[r] = fast_tanh(u1);
            }
        }

        const float4 fv = pv[8];   // wf0 wf1 bf -
        float4 o;
        o.x = fmaf(fv.x, ha[0], fmaf(fv.y, hb[0], fv.z));
        o.y = fmaf(fv.x, ha[1], fmaf(fv.y, hb[1], fv.z));
        o.z = fmaf(fv.x, ha[2], fmaf(fv.y, hb[2], fv.z));
        o.w = fmaf(fv.x, ha[3], fmaf(fv.y, hb[3], fv.z));
        out[item] = o;

        a = an; b = bn;
        item = next;
    }
}

extern "C" void kernel_launch(void* const* d_in, const int* in_sizes, int n_in,
                              void* d_out, int out_size)
{
    const float4* x = (const float4*)d_in[0];
    float4* out = (float4*)d_out;

    fraud_mlp_kernel<<<BLOCKS, THREADS>>>(
        x, out,
        (const float*)d_in[1], (const float*)d_in[2], (const float*)d_in[3],
        (const float*)d_in[4], (const float*)d_in[5], (const float*)d_in[6]);
}

// round 9
// speedup vs baseline: 1.0039x; 1.0039x over previous
#include <cuda_runtime.h>

// FraudDetectionModel R9: single graph node, 4096 CTAs x 4 grid-stride iters.
//  Clean test of prologue amortization (R8 was confounded by 64 regs/occ 42%):
//  - fold + __syncthreads paid ONCE per CTA, 4x fewer CTAs than R5/R7
//  - NO software prefetch / double buffer (that's what blew R8's registers);
//    cross-warp MLP from 6-8 resident CTAs/SM hides latency like in R2
//  - per-iter body = R2's proven minimal shape: 2 coalesced LDG.128
//    (nL=8; 8w*2*8=128 < 248 queue threshold), compute, 1 STG.128

#define BATCH   16777216
#define THREADS 256
#define BLOCKS  4096
#define ITERS   4
// work item = 4 rows; BLOCKS*THREADS*ITERS = 4,194,304 = BATCH/4 exactly.

__device__ __forceinline__ float fast_tanh(float x) {
    float y;
    asm("tanh.approx.f32 %0, %1;" : "=f"(y) : "f"(x));
    return y;
}

// smem param layout, 8 floats per layer:
//   layer l (0..3) at [8l]: w00 w01 w10 w11 b0 b1 pad pad
//   final at [32]:          wf0 wf1 bf pad
__global__ void __launch_bounds__(THREADS)
fraud_mlp_kernel(const float4* __restrict__ x,    // [B/2] row pairs
                 float4*       __restrict__ out,  // [B/4] quad outputs
                 const float*  __restrict__ Ws,   // [4,2,2]
                 const float*  __restrict__ bs,   // [4,2]
                 const float*  __restrict__ sc,   // [4,2]
                 const float*  __restrict__ sh,   // [4,2]
                 const float*  __restrict__ Wf,   // [1,2]
                 const float*  __restrict__ bf)   // [1]
{
    __shared__ __align__(16) float p[36];

    if (threadIdx.x == 0) {
        // layer 0 unchanged
        p[0] = __ldg(Ws + 0); p[1] = __ldg(Ws + 1);
        p[2] = __ldg(Ws + 2); p[3] = __ldg(Ws + 3);
        p[4] = __ldg(bs + 0); p[5] = __ldg(bs + 1);
        p[6] = 0.f; p[7] = 0.f;

        // layers 1..3: W'_l = W_l * diag(s_{l-1}); b'_l = W_l t_{l-1} + b_l
#pragma unroll
        for (int l = 1; l < 4; l++) {
            const float w00 = __ldg(Ws + l * 4 + 0), w01 = __ldg(Ws + l * 4 + 1);
            const float w10 = __ldg(Ws + l * 4 + 2), w11 = __ldg(Ws + l * 4 + 3);
            const float sp0 = __ldg(sc + (l - 1) * 2 + 0), sp1 = __ldg(sc + (l - 1) * 2 + 1);
            const float tp0 = __ldg(sh + (l - 1) * 2 + 0), tp1 = __ldg(sh + (l - 1) * 2 + 1);
            p[l * 8 + 0] = w00 * sp0;
            p[l * 8 + 1] = w01 * sp1;
            p[l * 8 + 2] = w10 * sp0;
            p[l * 8 + 3] = w11 * sp1;
            p[l * 8 + 4] = fmaf(w00, tp0, fmaf(w01, tp1, __ldg(bs + l * 2 + 0)));
            p[l * 8 + 5] = fmaf(w10, tp0, fmaf(w11, tp1, __ldg(bs + l * 2 + 1)));
            p[l * 8 + 6] = 0.f; p[l * 8 + 7] = 0.f;
        }

        // final: wf' = Wf * diag(s_3); bf' = Wf t_3 + bf
        const float s30 = __ldg(sc + 6), s31 = __ldg(sc + 7);
        const float t30 = __ldg(sh + 6), t31 = __ldg(sh + 7);
        const float f0 = __ldg(Wf + 0), f1 = __ldg(Wf + 1);
        p[32] = f0 * s30;
        p[33] = f1 * s31;
        p[34] = fmaf(f0, t30, fmaf(f1, t31, __ldg(bf)));
        p[35] = 0.0f;
    }
    __syncthreads();

    const float4* pv = reinterpret_cast<const float4*>(p);
    const int stride = BLOCKS * THREADS;            // 1,048,576 items
    int item = blockIdx.x * THREADS + threadIdx.x;

#pragma unroll 1
    for (int it = 0; it < ITERS; it++, item += stride) {
        const float4 a = x[2 * item + 0];
        const float4 b = x[2 * item + 1];

        float ha[4], hb[4];
        ha[0] = a.x; hb[0] = a.y;  ha[1] = a.z; hb[1] = a.w;
        ha[2] = b.x; hb[2] = b.y;  ha[3] = b.z; hb[3] = b.w;

#pragma unroll
        for (int l = 0; l < 4; l++) {
            const float4 wv = pv[2 * l + 0];   // w00 w01 w10 w11
            const float4 bv = pv[2 * l + 1];   // b0 b1 - -
#pragma unroll
            for (int r = 0; r < 4; r++) {
                float u0 = fmaf(wv.x, ha[r], fmaf(wv.y, hb[r], bv.x));
                float u1 = fmaf(wv.z, ha[r], fmaf(wv.w, hb[r], bv.y));
                ha[r] = fast_tanh(u0);
                hb[r] = fast_tanh(u1);
            }
        }

        const float4 fv = pv[8];   // wf0 wf1 bf -
        float4 o;
        o.x = fmaf(fv.x, ha[0], fmaf(fv.y, hb[0], fv.z));
        o.y = fmaf(fv.x, ha[1], fmaf(fv.y, hb[1], fv.z));
        o.z = fmaf(fv.x, ha[2], fmaf(fv.y, hb[2], fv.z));
        o.w = fmaf(fv.x, ha[3], fmaf(fv.y, hb[3], fv.z));
        out[item] = o;
    }
}

extern "C" void kernel_launch(void* const* d_in, const int* in_sizes, int n_in,
                              void* d_out, int out_size)
{
    const float4* x = (const float4*)d_in[0];
    float4* out = (float4*)d_out;

    fraud_mlp_kernel<<<BLOCKS, THREADS>>>(
        x, out,
        (const float*)d_in[1], (const float*)d_in[2], (const float*)d_in[3],
        (const float*)d_in[4], (const float*)d_in[5], (const float*)d_in[6]);
}

// round 10
// speedup vs baseline: 1.1649x; 1.1603x over previous
#include <cuda_runtime.h>

// FraudDetectionModel R10: single graph node, lane-parallel param fold.
//  R5/R7/R2 elimination: L1tex load and occupancy don't move kernel time;
//  the serialized thread0-fold prologue (~350-400 cyc/CTA over 16384 CTAs)
//  is the 67%->62% DRAM gap vs R2. Fix: 27 threads of warp 0 each compute
//  ONE folded param (parallel LDGs, <=2 FMA, 1 STS) -> prologue ~= one LDG
//  round trip. Body identical to R5 (4 rows/thread, occ ~89%).

#define BATCH   16777216
#define THREADS 256
#define ROWS_PER_THREAD 4

__device__ __forceinline__ float fast_tanh(float x) {
    float y;
    asm("tanh.approx.f32 %0, %1;" : "=f"(y) : "f"(x));
    return y;
}

// smem param layout, 8 floats per layer (16B-aligned):
//   layer l (0..3) at [8l]: w00 w01 w10 w11 b0 b1 pad pad
//   final at [32]:          wf0 wf1 bf pad
__global__ void __launch_bounds__(THREADS)
fraud_mlp_kernel(const float4* __restrict__ x,    // [B/2] row pairs
                 float4*       __restrict__ out,  // [B/4] quad outputs
                 const float*  __restrict__ Ws,   // [4,2,2]
                 const float*  __restrict__ bs,   // [4,2]
                 const float*  __restrict__ sc,   // [4,2]
                 const float*  __restrict__ sh,   // [4,2]
                 const float*  __restrict__ Wf,   // [1,2]
                 const float*  __restrict__ bf)   // [1]
{
    __shared__ __align__(16) float p[36];

    const int i = blockIdx.x * blockDim.x + threadIdx.x;

    // Data loads issued BEFORE the barrier (fold hides under LDG latency).
    const float4 xv0 = x[2 * i + 0];   // rows 0,1
    const float4 xv1 = x[2 * i + 1];   // rows 2,3

    // ---- lane-parallel fold: one folded param per thread ----
    const int t = threadIdx.x;
    if (t < 27) {
        if (t < 24) {
            const int l = t / 6;        // layer 0..3
            const int j = t % 6;        // 0..3 = W entries, 4..5 = bias rows
            float v;
            if (l == 0) {
                v = (j < 4) ? __ldg(Ws + j) : __ldg(bs + (j - 4));
            } else if (j < 4) {
                v = __ldg(Ws + l * 4 + j) * __ldg(sc + (l - 1) * 2 + (j & 1));
            } else {
                const int row = j - 4;
                v = fmaf(__ldg(Ws + l * 4 + row * 2 + 0), __ldg(sh + (l - 1) * 2 + 0),
                    fmaf(__ldg(Ws + l * 4 + row * 2 + 1), __ldg(sh + (l - 1) * 2 + 1),
                         __ldg(bs + l * 2 + row)));
            }
            p[l * 8 + j] = v;
        } else if (t == 24) {
            p[32] = __ldg(Wf + 0) * __ldg(sc + 6);
        } else if (t == 25) {
            p[33] = __ldg(Wf + 1) * __ldg(sc + 7);
        } else { // t == 26
            p[34] = fmaf(__ldg(Wf + 0), __ldg(sh + 6),
                    fmaf(__ldg(Wf + 1), __ldg(sh + 7), __ldg(bf)));
        }
    }
    __syncthreads();

    // All params into registers: 9 broadcast LDS.128 (pads unused).
    float pr[36];
    {
        const float4* pv = reinterpret_cast<const float4*>(p);
#pragma unroll
        for (int k = 0; k < 9; k++) {
            float4 v = pv[k];
            pr[4 * k + 0] = v.x;
            pr[4 * k + 1] = v.y;
            pr[4 * k + 2] = v.z;
            pr[4 * k + 3] = v.w;
        }
    }

    float ha[4], hb[4];
    ha[0] = xv0.x; hb[0] = xv0.y;  ha[1] = xv0.z; hb[1] = xv0.w;
    ha[2] = xv1.x; hb[2] = xv1.y;  ha[3] = xv1.z; hb[3] = xv1.w;

#pragma unroll
    for (int l = 0; l < 4; l++) {
        const float w00 = pr[l * 8 + 0], w01 = pr[l * 8 + 1];
        const float w10 = pr[l * 8 + 2], w11 = pr[l * 8 + 3];
        const float b0  = pr[l * 8 + 4], b1  = pr[l * 8 + 5];
#pragma unroll
        for (int r = 0; r < 4; r++) {
            float u0 = fmaf(w00, ha[r], fmaf(w01, hb[r], b0));
            float u1 = fmaf(w10, ha[r], fmaf(w11, hb[r], b1));
            ha[r] = fast_tanh(u0);
            hb[r] = fast_tanh(u1);
        }
    }

    const float wf0 = pr[32], wf1 = pr[33], bff = pr[34];

    float4 o;
    o.x = fmaf(wf0, ha[0], fmaf(wf1, hb[0], bff));
    o.y = fmaf(wf0, ha[1], fmaf(wf1, hb[1], bff));
    o.z = fmaf(wf0, ha[2], fmaf(wf1, hb[2], bff));
    o.w = fmaf(wf0, ha[3], fmaf(wf1, hb[3], bff));

    out[i] = o;
}

extern "C" void kernel_launch(void* const* d_in, const int* in_sizes, int n_in,
                              void* d_out, int out_size)
{
    const float4* x = (const float4*)d_in[0];
    float4* out = (float4*)d_out;

    const int nthreads = BATCH / ROWS_PER_THREAD;   // 4,194,304
    const int blocks = nthreads / THREADS;          // 16384
    fraud_mlp_kernel<<<blocks, THREADS>>>(
        x, out,
        (const float*)d_in[1], (const float*)d_in[2], (const float*)d_in[3],
        (const float*)d_in[4], (const float*)d_in[5], (const float*)d_in[6]);
}